// round 8
// baseline (speedup 1.0000x reference)
#include <cuda_runtime.h>
#include <math.h>
#include <stdint.h>

#define NB   32
#define CIN  64
#define COUT 128
#define TT   256
#define V    25
#define ICH  32
#define P    6400          // TT*V flat positions per (n, channel)
#define EPSF 1e-5f

// ---------------------------------------------------------------------------
// Scratch (device globals: allocation-free rule)
// ---------------------------------------------------------------------------
__device__ __align__(16) float g_res[(size_t)NB*COUT*P];   // residual fp32 [n][o][p]
__device__ __align__(16) float g_hT [(size_t)NB*P*COUT];   // h (tf32-rounded) [n][p][c]
__device__ __align__(16) float g_wtT[9*COUT*COUT];         // wt (tf32-rounded) [dt][o][c]
__device__ __align__(16) float g_bf [2*8*8*6*64];          // front B, fragment order [hl][wn][ks][nf][64]
__device__ float g_xm[NB*CIN*V];
__device__ float g_s[NB*ICH*V];

__device__ __forceinline__ float tf32r(float x) {
    uint32_t r;
    asm("cvt.rna.tf32.f32 %0, %1;" : "=r"(r) : "f"(x));
    return __uint_as_float(r);
}

__device__ __forceinline__ void mma_tf32(float* c, const uint32_t* a, const uint32_t* b) {
    asm volatile(
        "mma.sync.aligned.m16n8k8.row.col.f32.tf32.tf32.f32 "
        "{%0,%1,%2,%3}, {%4,%5,%6,%7}, {%8,%9}, {%0,%1,%2,%3};"
        : "+f"(c[0]), "+f"(c[1]), "+f"(c[2]), "+f"(c[3])
        : "r"(a[0]), "r"(a[1]), "r"(a[2]), "r"(a[3]), "r"(b[0]), "r"(b[1]));
}

// ---------------------------------------------------------------------------
// Kernel 1: xm[n,c,v] = mean_t x[n,c,t,v]
// ---------------------------------------------------------------------------
__global__ void k_mean(const float* __restrict__ x) {
    int b = blockIdx.x;
    const float* xp = x + (size_t)b * TT * V;
    int v = threadIdx.x & 31, tg = threadIdx.x >> 5;
    float s = 0.f;
    if (v < V) for (int t = tg; t < TT; t += 8) s += xp[t*V + v];
    __shared__ float sm[8][32];
    sm[tg][v] = s;
    __syncthreads();
    if (tg == 0 && v < V) {
        float tot = 0.f;
        #pragma unroll
        for (int g = 0; g < 8; g++) tot += sm[g][v];
        g_xm[b*V + v] = tot * (1.f / TT);
    }
}

// ---------------------------------------------------------------------------
// Kernel 2: s[n,i,v] = softmax_v( -(w2@xm + b2) )   (x1 cancels in softmax)
// ---------------------------------------------------------------------------
__global__ void k_soft(const float* __restrict__ w2, const float* __restrict__ b2) {
    int n = blockIdx.x >> 5, i = blockIdx.x & 31;
    int v = threadIdx.x;
    float z = -1e30f;
    if (v < V) {
        float acc = b2[i];
        const float* w  = w2 + i*CIN;
        const float* xm = g_xm + n*CIN*V;
        #pragma unroll 8
        for (int c = 0; c < CIN; c++) acc = fmaf(w[c], xm[c*V + v], acc);
        z = -acc;
    }
    float m = z;
    #pragma unroll
    for (int off = 16; off; off >>= 1) m = fmaxf(m, __shfl_xor_sync(~0u, m, off));
    float e = (v < V) ? expf(z - m) : 0.f;
    float ssum = e;
    #pragma unroll
    for (int off = 16; off; off >>= 1) ssum += __shfl_xor_sync(~0u, ssum, off);
    if (v < V) g_s[(n*ICH + i)*V + v] = e / ssum;
}

// ---------------------------------------------------------------------------
// Kernel 2b: wt -> [dt][o][c] fp32, tf32-rounded
// ---------------------------------------------------------------------------
__global__ void k_wprep(const float* __restrict__ wt) {
    int idx = blockIdx.x * 256 + threadIdx.x;
    if (idx >= 9*COUT*COUT) return;
    int dt = idx / (COUT*COUT), r = idx % (COUT*COUT);
    int o = r / COUT, c = r % COUT;
    g_wtT[idx] = tf32r(wt[((size_t)o*COUT + c)*9 + dt]);
}

// ---------------------------------------------------------------------------
// Kernel 2c: front B = [w3; w4; wr] in mma-fragment order, hi/lo tf32 split.
// g_bf[hl][wn 8][ks 8][nf 6][lane 32][2]:
//   col c = wn*48 + nf*8 + gq,  k = ks*8 + tg (+4 for second element)
// ---------------------------------------------------------------------------
__global__ void k_bprep(const float* __restrict__ w3, const float* __restrict__ w4,
                        const float* __restrict__ wr) {
    int idx = blockIdx.x * 256 + threadIdx.x;
    if (idx >= 2*8*8*6*64) return;
    int j2 = idx & 63;
    int nf = (idx >> 6) % 6;
    int ks = (idx / 384) % 8;
    int wn = (idx / 3072) % 8;
    int hl = idx / 24576;
    int lane = j2 >> 1, half = j2 & 1;
    int gq = lane >> 2, tg = lane & 3;
    int c = wn*48 + nf*8 + gq;
    int k = ks*8 + tg + half*4;
    float v;
    if      (c < 128) v = w3[c*64 + k];
    else if (c < 256) v = w4[(c-128)*64 + k];
    else              v = wr[(c-256)*64 + k];
    float hi = tf32r(v);
    g_bf[idx] = hl ? tf32r(v - hi) : hi;
}

// ---------------------------------------------------------------------------
// Kernel 3: front end. Per block (n, ptile of 50 = 2 t-rows):
//   GEMM Y[50(pad64), 384] = X^T x [w3;w4;wr]^T, 3-term tf32 split precision
//   (As holds [x_hi | x_lo], K=128; B from fragment-order gmem).
//   Epilogue: softmax-y1, A-mix, BN1+ReLU -> g_hT; BNr -> g_res.
// 256 threads = 8 warps 1M x 8N, warp tile 64x48. 2 CTAs/SM.
// ---------------------------------------------------------------------------
#define KST 140    // As stride: frag-load banks 12*gq + tg, all distinct mod 32
#define YST 385
#define HST 129

__global__ void __launch_bounds__(256, 2) k_front(
    const float* __restrict__ x,  const float* __restrict__ A,
    const float* __restrict__ b3, const float* __restrict__ b4,
    const float* __restrict__ br,
    const float* __restrict__ bn1g, const float* __restrict__ bn1b,
    const float* __restrict__ bn1m, const float* __restrict__ bn1v,
    const float* __restrict__ bnrg, const float* __restrict__ bnrb,
    const float* __restrict__ bnrm, const float* __restrict__ bnrv)
{
    extern __shared__ __align__(16) float dsm[];
    __shared__ float sA[625], ss[800];
    __shared__ float sb3[128], sb4[128], sc1[128], so1[128], scr[128], sofr[128];

    const int tid = threadIdx.x;
    const int n = blockIdx.y;
    const int pbase = blockIdx.x * 50;

    for (int idx = tid; idx < 625; idx += 256) sA[idx] = A[idx];
    for (int idx = tid; idx < 800; idx += 256) ss[idx] = g_s[n*800 + idx];
    if (tid < 128) {
        float s1 = bn1g[tid] / sqrtf(bn1v[tid] + EPSF);
        sc1[tid] = s1;
        so1[tid] = bn1b[tid] - bn1m[tid]*s1;
        float sr = bnrg[tid] / sqrtf(bnrv[tid] + EPSF);
        scr[tid] = sr;
        sofr[tid] = sr*br[tid] + (bnrb[tid] - bnrm[tid]*sr);
        sb3[tid] = b3[tid];
        sb4[tid] = b4[tid];
    }

    float* As = dsm;   // [64][KST]: cols 0..64 = x_hi, 64..128 = x_lo

    // stage A = X^T with hi/lo split (transpose during store)
    const float* xn = x + (size_t)n*CIN*P + pbase;
    for (int idx = tid; idx < 1600; idx += 256) {
        int c = idx / 25, j = idx % 25;
        float2 v = *reinterpret_cast<const float2*>(xn + (size_t)c*P + j*2);
        int r = j*2;
        float h0 = tf32r(v.x), h1 = tf32r(v.y);
        As[r*KST + c]            = h0;
        As[r*KST + 64 + c]       = tf32r(v.x - h0);
        As[(r+1)*KST + c]        = h1;
        As[(r+1)*KST + 64 + c]   = tf32r(v.y - h1);
    }
    for (int idx = tid; idx < 14*128; idx += 256) {
        int r = 50 + idx / 128, c = idx % 128;
        As[r*KST + c] = 0.f;
    }
    __syncthreads();

    // MMA: 8 warps, warp = one 48-col N block, M=64
    const int wid = tid >> 5, lid = tid & 31;
    const int gq = lid >> 2, tg = lid & 3;

    float acc[4][6][4];
    #pragma unroll
    for (int mf = 0; mf < 4; mf++)
        #pragma unroll
        for (int nf = 0; nf < 6; nf++)
            #pragma unroll
            for (int q = 0; q < 4; q++) acc[mf][nf][q] = 0.f;

    const float* bf_hi = g_bf + wid*3072 + lid*2;
    const float* bf_lo = bf_hi + 24576;
    const float* Ab = As + gq*KST + tg;

    // passes 1+2: (x_hi + x_lo) * w_hi   (shared bf)
    #pragma unroll
    for (int ks = 0; ks < 8; ks++) {
        uint32_t bf[6][2];
        #pragma unroll
        for (int nf = 0; nf < 6; nf++) {
            float2 b2v = *reinterpret_cast<const float2*>(bf_hi + ks*384 + nf*64);
            bf[nf][0] = __float_as_uint(b2v.x);
            bf[nf][1] = __float_as_uint(b2v.y);
        }
        #pragma unroll
        for (int g = 0; g < 2; g++) {
            #pragma unroll
            for (int mf = 0; mf < 4; mf++) {
                const float* ap = Ab + mf*16*KST + g*64 + ks*8;
                uint32_t af[4];
                af[0] = __float_as_uint(ap[0]);
                af[1] = __float_as_uint(ap[8*KST]);
                af[2] = __float_as_uint(ap[4]);
                af[3] = __float_as_uint(ap[8*KST + 4]);
                #pragma unroll
                for (int nf = 0; nf < 6; nf++) mma_tf32(acc[mf][nf], af, bf[nf]);
            }
        }
    }
    // pass 3: x_hi * w_lo
    #pragma unroll
    for (int ks = 0; ks < 8; ks++) {
        uint32_t bf[6][2];
        #pragma unroll
        for (int nf = 0; nf < 6; nf++) {
            float2 b2v = *reinterpret_cast<const float2*>(bf_lo + ks*384 + nf*64);
            bf[nf][0] = __float_as_uint(b2v.x);
            bf[nf][1] = __float_as_uint(b2v.y);
        }
        #pragma unroll
        for (int mf = 0; mf < 4; mf++) {
            const float* ap = Ab + mf*16*KST + ks*8;
            uint32_t af[4];
            af[0] = __float_as_uint(ap[0]);
            af[1] = __float_as_uint(ap[8*KST]);
            af[2] = __float_as_uint(ap[4]);
            af[3] = __float_as_uint(ap[8*KST + 4]);
            #pragma unroll
            for (int nf = 0; nf < 6; nf++) mma_tf32(acc[mf][nf], af, bf[nf]);
        }
    }
    __syncthreads();   // A staging consumed

    // frags -> Ys[50][YST]
    float* Ys = dsm;
    float* Hs = dsm + 50*YST;
    #pragma unroll
    for (int mf = 0; mf < 4; mf++) {
        int r0 = mf*16 + gq;
        #pragma unroll
        for (int nf = 0; nf < 6; nf++) {
            int c0 = wid*48 + nf*8 + tg*2;
            if (r0 < 50) {
                Ys[r0*YST + c0]     = acc[mf][nf][0];
                Ys[r0*YST + c0 + 1] = acc[mf][nf][1];
            }
            if (r0 + 8 < 50) {
                Ys[(r0+8)*YST + c0]     = acc[mf][nf][2];
                Ys[(r0+8)*YST + c0 + 1] = acc[mf][nf][3];
            }
        }
    }
    __syncthreads();

    // epilogue: thread = (o, th), th in {0,1}
    float pr[V];
    {
        const int o = tid & 127, th = tid >> 7;
        float p3[V], p4[V];
        const float* yrow = Ys + (th*25)*YST;
        float b4v = sb4[o];
        #pragma unroll
        for (int v = 0; v < V; v++) {
            p3[v] = yrow[v*YST + o];
            p4[v] = yrow[v*YST + 128 + o] + b4v;
            pr[v] = yrow[v*YST + 256 + o];
        }
        float y1 = sb3[o];
        const float* sv = ss + (o & 31)*V;
        #pragma unroll
        for (int v = 0; v < V; v++) y1 = fmaf(sv[v], p3[v], y1);

        float s1 = sc1[o], o1 = so1[o];
        #pragma unroll 5
        for (int u = 0; u < V; u++) {
            float a = y1;
            const float* Ar = sA + u*V;
            #pragma unroll
            for (int v = 0; v < V; v++) a = fmaf(Ar[v], p4[v], a);
            float h = fmaf(s1, a, o1);
            Hs[(th*25 + u)*HST + o] = h > 0.f ? h : 0.f;
        }
        float sr = scr[o], ofr = sofr[o];
        #pragma unroll
        for (int v = 0; v < V; v++) pr[v] = fmaf(sr, pr[v], ofr);
    }
    __syncthreads();

    // drain h -> g_hT (coalesced, tf32-rounded)
    {
        float* hdst = g_hT + ((size_t)n*P + pbase)*COUT;
        for (int idx = tid; idx < 6400; idx += 256) {
            int r = idx >> 7, o = idx & 127;
            hdst[(size_t)r*COUT + o] = tf32r(Hs[r*HST + o]);
        }
    }
    __syncthreads();

    // res through Hs, then transposed coalesced drain to g_res[n][o][p]
    {
        const int o = tid & 127, th = tid >> 7;
        #pragma unroll
        for (int v = 0; v < V; v++) Hs[(th*25 + v)*HST + o] = pr[v];
    }
    __syncthreads();
    {
        for (int idx = tid; idx < 6400; idx += 256) {
            int o = idx / 50, q = idx % 50;
            g_res[((size_t)n*COUT + o)*P + pbase + q] = Hs[q*HST + o];
        }
    }
}

// ---------------------------------------------------------------------------
// Kernel 4: temporal conv as 9 shifted GEMMs via mma.sync tf32 (unchanged)
// ---------------------------------------------------------------------------
#define AST 36
#define DST 133
#define AROWS 328

__global__ void __launch_bounds__(256, 2) k_tcn_mma(
    const float* __restrict__ bt,
    const float* __restrict__ bn2g, const float* __restrict__ bn2b,
    const float* __restrict__ bn2m, const float* __restrict__ bn2v,
    float* __restrict__ out)
{
    extern __shared__ __align__(16) float dsm[];
    float* As = dsm;                   // [AROWS][AST]
    float* Bs = dsm + AROWS*AST;       // [128][AST]
    __shared__ float s_s2[COUT], s_o2[COUT];

    const int tid = threadIdx.x, wid = tid >> 5, lid = tid & 31;
    const int gq = lid >> 2, tg = lid & 3;
    const int wm = wid >> 1, wn = wid & 1;
    const int n = blockIdx.y;
    const int pbase = blockIdx.x * 128;

    if (tid < COUT) {
        float s2 = bn2g[tid] / sqrtf(bn2v[tid] + EPSF);
        s_s2[tid] = s2;
        s_o2[tid] = bn2b[tid] - bn2m[tid]*s2 + s2*bt[tid];
    }

    float acc[2][8][4];
    #pragma unroll
    for (int mf = 0; mf < 2; mf++)
        #pragma unroll
        for (int nf = 0; nf < 8; nf++)
            #pragma unroll
            for (int q = 0; q < 4; q++) acc[mf][nf][q] = 0.f;

    const float* hbase = g_hT + (size_t)n * P * COUT;

    #pragma unroll 1
    for (int ck = 0; ck < 4; ck++) {
        __syncthreads();
        #pragma unroll 1
        for (int v4 = tid; v4 < AROWS*8; v4 += 256) {
            int r = v4 >> 3, q = v4 & 7;
            int gp = pbase - 100 + r;
            float4 val = make_float4(0.f, 0.f, 0.f, 0.f);
            if ((unsigned)gp < (unsigned)P)
                val = *reinterpret_cast<const float4*>(hbase + (size_t)gp*COUT + ck*32 + q*4);
            *reinterpret_cast<float4*>(As + r*AST + q*4) = val;
        }

        #pragma unroll 1
        for (int dt = 0; dt < 9; dt++) {
            if (dt) __syncthreads();
            #pragma unroll
            for (int i = 0; i < 4; i++) {
                int v4 = tid + i*256;
                int r = v4 >> 3, q = v4 & 7;
                *reinterpret_cast<float4*>(Bs + r*AST + q*4) =
                    *reinterpret_cast<const float4*>(
                        g_wtT + ((size_t)dt*COUT + r)*COUT + ck*32 + q*4);
            }
            __syncthreads();

            const float* Aw = As + (dt*25 + wm*32 + gq)*AST + tg;
            const float* Bw = Bs + (wn*64 + gq)*AST + tg;
            #pragma unroll
            for (int ks = 0; ks < 4; ks++) {
                int k0 = ks*8;
                uint32_t af[2][4];
                #pragma unroll
                for (int mf = 0; mf < 2; mf++) {
                    const float* ap = Aw + mf*16*AST + k0;
                    af[mf][0] = __float_as_uint(ap[0]);
                    af[mf][1] = __float_as_uint(ap[8*AST]);
                    af[mf][2] = __float_as_uint(ap[4]);
                    af[mf][3] = __float_as_uint(ap[8*AST + 4]);
                }
                uint32_t bf[8][2];
                #pragma unroll
                for (int nf = 0; nf < 8; nf++) {
                    const float* bp = Bw + nf*8*AST + k0;
                    bf[nf][0] = __float_as_uint(bp[0]);
                    bf[nf][1] = __float_as_uint(bp[4]);
                }
                #pragma unroll
                for (int mf = 0; mf < 2; mf++)
                    #pragma unroll
                    for (int nf = 0; nf < 8; nf++)
                        mma_tf32(acc[mf][nf], af[mf], bf[nf]);
            }
        }
    }

    __syncthreads();
    float* Ds = dsm;   // [128 p][DST]
    #pragma unroll
    for (int mf = 0; mf < 2; mf++) {
        int r0 = wm*32 + mf*16 + gq;
        #pragma unroll
        for (int nf = 0; nf < 8; nf++) {
            int c0 = wn*64 + nf*8 + tg*2;
            Ds[r0*DST + c0]       = acc[mf][nf][0];
            Ds[r0*DST + c0 + 1]   = acc[mf][nf][1];
            Ds[(r0+8)*DST + c0]   = acc[mf][nf][2];
            Ds[(r0+8)*DST + c0+1] = acc[mf][nf][3];
        }
    }
    __syncthreads();

    {
        int o = tid >> 1, half = tid & 1;
        float s2 = s_s2[o], o2 = s_o2[o];
        size_t gbase = ((size_t)n*COUT + o)*P + pbase + half*64;
        const float4* rp = reinterpret_cast<const float4*>(g_res + gbase);
        float4*       op = reinterpret_cast<float4*>(out + gbase);
        #pragma unroll 4
        for (int j4 = 0; j4 < 16; j4++) {
            int pl = half*64 + j4*4;
            float4 r = rp[j4];
            float4 w;
            w.x = fmaf(s2, Ds[(pl+0)*DST + o], o2) + r.x;
            w.y = fmaf(s2, Ds[(pl+1)*DST + o], o2) + r.y;
            w.z = fmaf(s2, Ds[(pl+2)*DST + o], o2) + r.z;
            w.w = fmaf(s2, Ds[(pl+3)*DST + o], o2) + r.w;
            w.x = w.x > 0.f ? w.x : 0.f;
            w.y = w.y > 0.f ? w.y : 0.f;
            w.z = w.z > 0.f ? w.z : 0.f;
            w.w = w.w > 0.f ? w.w : 0.f;
            op[j4] = w;
        }
    }
}

// ---------------------------------------------------------------------------
extern "C" void kernel_launch(void* const* d_in, const int* in_sizes, int n_in,
                              void* d_out, int out_size) {
    const float* x    = (const float*)d_in[0];
    const float* A    = (const float*)d_in[1];
    // d_in[2], d_in[3] = w1, b1 -- cancel in softmax
    const float* w2   = (const float*)d_in[4];
    const float* b2   = (const float*)d_in[5];
    const float* w3   = (const float*)d_in[6];
    const float* b3   = (const float*)d_in[7];
    const float* w4   = (const float*)d_in[8];
    const float* b4   = (const float*)d_in[9];
    const float* bn1g = (const float*)d_in[10];
    const float* bn1b = (const float*)d_in[11];
    const float* bn1m = (const float*)d_in[12];
    const float* bn1v = (const float*)d_in[13];
    const float* wt   = (const float*)d_in[14];
    const float* bt   = (const float*)d_in[15];
    const float* bn2g = (const float*)d_in[16];
    const float* bn2b = (const float*)d_in[17];
    const float* bn2m = (const float*)d_in[18];
    const float* bn2v = (const float*)d_in[19];
    const float* wr   = (const float*)d_in[20];
    const float* br   = (const float*)d_in[21];
    const float* bnrg = (const float*)d_in[22];
    const float* bnrb = (const float*)d_in[23];
    const float* bnrm = (const float*)d_in[24];
    const float* bnrv = (const float*)d_in[25];
    float* out = (float*)d_out;

    static const int AS_F   = 64*KST;                 // 8960
    static const int EPI_F  = 50*YST + 50*HST;        // 19250 + 6450 = 25700
    static const int FRONT_SMEM = (AS_F > EPI_F ? AS_F : EPI_F) * 4;   // 102800 B
    static const int TCN_SMEM   = (128*DST > AROWS*AST + 128*AST ?
                                   128*DST : AROWS*AST + 128*AST) * 4; // 68096 B
    cudaFuncSetAttribute(k_front,   cudaFuncAttributeMaxDynamicSharedMemorySize, FRONT_SMEM);
    cudaFuncSetAttribute(k_tcn_mma, cudaFuncAttributeMaxDynamicSharedMemorySize, TCN_SMEM);

    k_mean<<<NB*CIN, 256>>>(x);
    k_soft<<<NB*ICH, 32>>>(w2, b2);
    k_wprep<<<(9*COUT*COUT + 255)/256, 256>>>(wt);
    k_bprep<<<(2*8*8*6*64 + 255)/256, 256>>>(w3, w4, wr);
    k_front<<<dim3(128, NB), 256, FRONT_SMEM>>>(
        x, A, b3, b4, br,
        bn1g, bn1b, bn1m, bn1v, bnrg, bnrb, bnrm, bnrv);
    k_tcn_mma<<<dim3(50, NB), 256, TCN_SMEM>>>(
        bt, bn2g, bn2b, bn2m, bn2v, out);
}

// round 9
// speedup vs baseline: 1.0364x; 1.0364x over previous
#include <cuda_runtime.h>
#include <math.h>
#include <stdint.h>

#define NB   32
#define CIN  64
#define COUT 128
#define TT   256
#define V    25
#define ICH  32
#define P    6400          // TT*V flat positions per (n, channel)
#define EPSF 1e-5f

// ---------------------------------------------------------------------------
// Scratch (device globals: allocation-free rule)
// ---------------------------------------------------------------------------
__device__ __align__(16) float g_resT[(size_t)NB*P*COUT];  // residual fp32 [n][p][o]
__device__ __align__(16) float g_hT [(size_t)NB*P*COUT];   // h (tf32-rounded) [n][p][c]
__device__ __align__(16) float g_wtT[9*COUT*COUT];         // wt (tf32-rounded) [dt][o][c]
__device__ __align__(16) float g_bf [2*8*8*6*64];          // front B, frag order [hl][wn][ks][nf][64]
__device__ float g_xm[NB*CIN*V];
__device__ float g_s[NB*ICH*V];

__device__ __forceinline__ float tf32r(float x) {
    uint32_t r;
    asm("cvt.rna.tf32.f32 %0, %1;" : "=r"(r) : "f"(x));
    return __uint_as_float(r);
}

__device__ __forceinline__ void mma_tf32(float* c, const uint32_t* a, const uint32_t* b) {
    asm volatile(
        "mma.sync.aligned.m16n8k8.row.col.f32.tf32.tf32.f32 "
        "{%0,%1,%2,%3}, {%4,%5,%6,%7}, {%8,%9}, {%0,%1,%2,%3};"
        : "+f"(c[0]), "+f"(c[1]), "+f"(c[2]), "+f"(c[3])
        : "r"(a[0]), "r"(a[1]), "r"(a[2]), "r"(a[3]), "r"(b[0]), "r"(b[1]));
}

// ---------------------------------------------------------------------------
// Kernel 1: xm[n,c,v] = mean_t x[n,c,t,v]
// ---------------------------------------------------------------------------
__global__ void k_mean(const float* __restrict__ x) {
    int b = blockIdx.x;
    const float* xp = x + (size_t)b * TT * V;
    int v = threadIdx.x & 31, tg = threadIdx.x >> 5;
    float s = 0.f;
    if (v < V) for (int t = tg; t < TT; t += 8) s += xp[t*V + v];
    __shared__ float sm[8][32];
    sm[tg][v] = s;
    __syncthreads();
    if (tg == 0 && v < V) {
        float tot = 0.f;
        #pragma unroll
        for (int g = 0; g < 8; g++) tot += sm[g][v];
        g_xm[b*V + v] = tot * (1.f / TT);
    }
}

// ---------------------------------------------------------------------------
// Kernel 2: s[n,i,v] = softmax_v( -(w2@xm + b2) )   (x1 cancels in softmax)
// ---------------------------------------------------------------------------
__global__ void k_soft(const float* __restrict__ w2, const float* __restrict__ b2) {
    int n = blockIdx.x >> 5, i = blockIdx.x & 31;
    int v = threadIdx.x;
    float z = -1e30f;
    if (v < V) {
        float acc = b2[i];
        const float* w  = w2 + i*CIN;
        const float* xm = g_xm + n*CIN*V;
        #pragma unroll 8
        for (int c = 0; c < CIN; c++) acc = fmaf(w[c], xm[c*V + v], acc);
        z = -acc;
    }
    float m = z;
    #pragma unroll
    for (int off = 16; off; off >>= 1) m = fmaxf(m, __shfl_xor_sync(~0u, m, off));
    float e = (v < V) ? expf(z - m) : 0.f;
    float ssum = e;
    #pragma unroll
    for (int off = 16; off; off >>= 1) ssum += __shfl_xor_sync(~0u, ssum, off);
    if (v < V) g_s[(n*ICH + i)*V + v] = e / ssum;
}

// ---------------------------------------------------------------------------
// Kernel 2b: wt -> [dt][o][c] fp32, tf32-rounded
// ---------------------------------------------------------------------------
__global__ void k_wprep(const float* __restrict__ wt) {
    int idx = blockIdx.x * 256 + threadIdx.x;
    if (idx >= 9*COUT*COUT) return;
    int dt = idx / (COUT*COUT), r = idx % (COUT*COUT);
    int o = r / COUT, c = r % COUT;
    g_wtT[idx] = tf32r(wt[((size_t)o*COUT + c)*9 + dt]);
}

// ---------------------------------------------------------------------------
// Kernel 2c: front B = [w3; w4; wr] in mma-fragment order, hi/lo tf32 split
// ---------------------------------------------------------------------------
__global__ void k_bprep(const float* __restrict__ w3, const float* __restrict__ w4,
                        const float* __restrict__ wr) {
    int idx = blockIdx.x * 256 + threadIdx.x;
    if (idx >= 2*8*8*6*64) return;
    int j2 = idx & 63;
    int nf = (idx >> 6) % 6;
    int ks = (idx / 384) % 8;
    int wn = (idx / 3072) % 8;
    int hl = idx / 24576;
    int lane = j2 >> 1, half = j2 & 1;
    int gq = lane >> 2, tg = lane & 3;
    int c = wn*48 + nf*8 + gq;
    int k = ks*8 + tg + half*4;
    float v;
    if      (c < 128) v = w3[c*64 + k];
    else if (c < 256) v = w4[(c-128)*64 + k];
    else              v = wr[(c-256)*64 + k];
    float hi = tf32r(v);
    g_bf[idx] = hl ? tf32r(v - hi) : hi;
}

// ---------------------------------------------------------------------------
// Kernel 3: front end. Per block (n, ptile of 50): 3-term tf32 split GEMM
//   Y[50(pad64),384] = X^T x [w3;w4;wr]^T; epilogue via transposed Yt smem:
//   softmax-y1, A-mix, BN1+ReLU -> g_hT (direct coalesced), BNr -> g_resT.
// 256 threads = 8 warps (1M x 8N), warp tile 64x48. 2 CTAs/SM.
// ---------------------------------------------------------------------------
#define KST 140    // As stride: frag-load banks 12*gq + tg, distinct mod 32
#define YTS 53     // Yt stride (odd -> epilogue reads conflict-free)

__global__ void __launch_bounds__(256, 2) k_front(
    const float* __restrict__ x,  const float* __restrict__ A,
    const float* __restrict__ b3, const float* __restrict__ b4,
    const float* __restrict__ br,
    const float* __restrict__ bn1g, const float* __restrict__ bn1b,
    const float* __restrict__ bn1m, const float* __restrict__ bn1v,
    const float* __restrict__ bnrg, const float* __restrict__ bnrb,
    const float* __restrict__ bnrm, const float* __restrict__ bnrv)
{
    extern __shared__ __align__(16) float dsm[];
    __shared__ float sA[625], ss[800];
    __shared__ float sb3[128], sb4[128], sc1[128], so1[128], scr[128], sofr[128];

    const int tid = threadIdx.x;
    const int n = blockIdx.y;
    const int pbase = blockIdx.x * 50;

    for (int idx = tid; idx < 625; idx += 256) sA[idx] = A[idx];
    for (int idx = tid; idx < 800; idx += 256) ss[idx] = g_s[n*800 + idx];
    if (tid < 128) {
        float s1 = bn1g[tid] / sqrtf(bn1v[tid] + EPSF);
        sc1[tid] = s1;
        so1[tid] = bn1b[tid] - bn1m[tid]*s1;
        float sr = bnrg[tid] / sqrtf(bnrv[tid] + EPSF);
        scr[tid] = sr;
        sofr[tid] = sr*br[tid] + (bnrb[tid] - bnrm[tid]*sr);
        sb3[tid] = b3[tid];
        sb4[tid] = b4[tid];
    }

    float* As = dsm;   // [64][KST]: cols 0..64 = x_hi, 64..128 = x_lo

    // stage A = X^T with hi/lo split (transpose during store)
    const float* xn = x + (size_t)n*CIN*P + pbase;
    for (int idx = tid; idx < 1600; idx += 256) {
        int c = idx / 25, j = idx % 25;
        float2 v = *reinterpret_cast<const float2*>(xn + (size_t)c*P + j*2);
        int r = j*2;
        float h0 = tf32r(v.x), h1 = tf32r(v.y);
        As[r*KST + c]            = h0;
        As[r*KST + 64 + c]       = tf32r(v.x - h0);
        As[(r+1)*KST + c]        = h1;
        As[(r+1)*KST + 64 + c]   = tf32r(v.y - h1);
    }
    for (int idx = tid; idx < 14*128; idx += 256) {
        int r = 50 + idx / 128, c = idx % 128;
        As[r*KST + c] = 0.f;
    }
    __syncthreads();

    const int wid = tid >> 5, lid = tid & 31;
    const int gq = lid >> 2, tg = lid & 3;

    float acc[4][6][4];
    #pragma unroll
    for (int mf = 0; mf < 4; mf++)
        #pragma unroll
        for (int nf = 0; nf < 6; nf++)
            #pragma unroll
            for (int q = 0; q < 4; q++) acc[mf][nf][q] = 0.f;

    const float* bf_hi = g_bf + wid*3072 + lid*2;
    const float* bf_lo = bf_hi + 24576;
    const float* Ab = As + gq*KST + tg;

    // passes 1+2: (x_hi + x_lo) * w_hi
    #pragma unroll
    for (int ks = 0; ks < 8; ks++) {
        uint32_t bf[6][2];
        #pragma unroll
        for (int nf = 0; nf < 6; nf++) {
            float2 b2v = *reinterpret_cast<const float2*>(bf_hi + ks*384 + nf*64);
            bf[nf][0] = __float_as_uint(b2v.x);
            bf[nf][1] = __float_as_uint(b2v.y);
        }
        #pragma unroll
        for (int g = 0; g < 2; g++) {
            #pragma unroll
            for (int mf = 0; mf < 4; mf++) {
                const float* ap = Ab + mf*16*KST + g*64 + ks*8;
                uint32_t af[4];
                af[0] = __float_as_uint(ap[0]);
                af[1] = __float_as_uint(ap[8*KST]);
                af[2] = __float_as_uint(ap[4]);
                af[3] = __float_as_uint(ap[8*KST + 4]);
                #pragma unroll
                for (int nf = 0; nf < 6; nf++) mma_tf32(acc[mf][nf], af, bf[nf]);
            }
        }
    }
    // pass 3: x_hi * w_lo
    #pragma unroll
    for (int ks = 0; ks < 8; ks++) {
        uint32_t bf[6][2];
        #pragma unroll
        for (int nf = 0; nf < 6; nf++) {
            float2 b2v = *reinterpret_cast<const float2*>(bf_lo + ks*384 + nf*64);
            bf[nf][0] = __float_as_uint(b2v.x);
            bf[nf][1] = __float_as_uint(b2v.y);
        }
        #pragma unroll
        for (int mf = 0; mf < 4; mf++) {
            const float* ap = Ab + mf*16*KST + ks*8;
            uint32_t af[4];
            af[0] = __float_as_uint(ap[0]);
            af[1] = __float_as_uint(ap[8*KST]);
            af[2] = __float_as_uint(ap[4]);
            af[3] = __float_as_uint(ap[8*KST + 4]);
            #pragma unroll
            for (int nf = 0; nf < 6; nf++) mma_tf32(acc[mf][nf], af, bf[nf]);
        }
    }
    __syncthreads();   // A staging consumed

    // frags -> Yt[384 cols][YTS] (transposed)
    float* Yt = dsm;
    #pragma unroll
    for (int mf = 0; mf < 4; mf++) {
        int r0 = mf*16 + gq;
        #pragma unroll
        for (int nf = 0; nf < 6; nf++) {
            int c0 = wid*48 + nf*8 + tg*2;
            if (r0 < 50) {
                Yt[c0*YTS + r0]     = acc[mf][nf][0];
                Yt[(c0+1)*YTS + r0] = acc[mf][nf][1];
            }
            if (r0 + 8 < 50) {
                Yt[c0*YTS + r0 + 8]     = acc[mf][nf][2];
                Yt[(c0+1)*YTS + r0 + 8] = acc[mf][nf][3];
            }
        }
    }
    __syncthreads();

    // epilogue: thread = (o, th), th in {0,1}; direct coalesced drains
    {
        const int o = tid & 127, th = tid >> 7;
        float p3[V], p4[V], pr[V];
        const float* y3 = Yt + o*YTS + th*25;
        const float* y4 = Yt + (128 + o)*YTS + th*25;
        const float* yr = Yt + (256 + o)*YTS + th*25;
        float b4v = sb4[o];
        #pragma unroll
        for (int v = 0; v < V; v++) {
            p3[v] = y3[v];
            p4[v] = y4[v] + b4v;
            pr[v] = yr[v];
        }
        float y1 = sb3[o];
        const float* sv = ss + (o & 31)*V;
        #pragma unroll
        for (int v = 0; v < V; v++) y1 = fmaf(sv[v], p3[v], y1);

        float s1 = sc1[o], o1 = so1[o];
        float* hdst = g_hT + ((size_t)n*P + pbase)*COUT;
        #pragma unroll 5
        for (int u = 0; u < V; u++) {
            float a = y1;
            const float* Ar = sA + u*V;
            #pragma unroll
            for (int v = 0; v < V; v++) a = fmaf(Ar[v], p4[v], a);
            float h = fmaf(s1, a, o1);
            hdst[(size_t)(th*25 + u)*COUT + o] = tf32r(h > 0.f ? h : 0.f);
        }
        float sr = scr[o], ofr = sofr[o];
        float* rdst = g_resT + ((size_t)n*P + pbase)*COUT;
        #pragma unroll
        for (int v = 0; v < V; v++)
            rdst[(size_t)(th*25 + v)*COUT + o] = fmaf(sr, pr[v], ofr);
    }
}

// ---------------------------------------------------------------------------
// Kernel 4: temporal conv as 9 shifted GEMMs via mma.sync tf32.
// Epilogue: BN2 + residual (g_resT, fragment-space add) + ReLU, Ds transpose,
// coalesced out writes.
// ---------------------------------------------------------------------------
#define AST 36
#define DST 133
#define AROWS 328

__global__ void __launch_bounds__(256, 2) k_tcn_mma(
    const float* __restrict__ bt,
    const float* __restrict__ bn2g, const float* __restrict__ bn2b,
    const float* __restrict__ bn2m, const float* __restrict__ bn2v,
    float* __restrict__ out)
{
    extern __shared__ __align__(16) float dsm[];
    float* As = dsm;                   // [AROWS][AST]
    float* Bs = dsm + AROWS*AST;       // [128][AST]
    __shared__ float s_s2[COUT], s_o2[COUT];

    const int tid = threadIdx.x, wid = tid >> 5, lid = tid & 31;
    const int gq = lid >> 2, tg = lid & 3;
    const int wm = wid >> 1, wn = wid & 1;
    const int n = blockIdx.y;
    const int pbase = blockIdx.x * 128;

    if (tid < COUT) {
        float s2 = bn2g[tid] / sqrtf(bn2v[tid] + EPSF);
        s_s2[tid] = s2;
        s_o2[tid] = bn2b[tid] - bn2m[tid]*s2 + s2*bt[tid];
    }

    float acc[2][8][4];
    #pragma unroll
    for (int mf = 0; mf < 2; mf++)
        #pragma unroll
        for (int nf = 0; nf < 8; nf++)
            #pragma unroll
            for (int q = 0; q < 4; q++) acc[mf][nf][q] = 0.f;

    const float* hbase = g_hT + (size_t)n * P * COUT;

    #pragma unroll 1
    for (int ck = 0; ck < 4; ck++) {
        __syncthreads();
        #pragma unroll 1
        for (int v4 = tid; v4 < AROWS*8; v4 += 256) {
            int r = v4 >> 3, q = v4 & 7;
            int gp = pbase - 100 + r;
            float4 val = make_float4(0.f, 0.f, 0.f, 0.f);
            if ((unsigned)gp < (unsigned)P)
                val = *reinterpret_cast<const float4*>(hbase + (size_t)gp*COUT + ck*32 + q*4);
            *reinterpret_cast<float4*>(As + r*AST + q*4) = val;
        }

        #pragma unroll 1
        for (int dt = 0; dt < 9; dt++) {
            if (dt) __syncthreads();
            #pragma unroll
            for (int i = 0; i < 4; i++) {
                int v4 = tid + i*256;
                int r = v4 >> 3, q = v4 & 7;
                *reinterpret_cast<float4*>(Bs + r*AST + q*4) =
                    *reinterpret_cast<const float4*>(
                        g_wtT + ((size_t)dt*COUT + r)*COUT + ck*32 + q*4);
            }
            __syncthreads();

            const float* Aw = As + (dt*25 + wm*32 + gq)*AST + tg;
            const float* Bw = Bs + (wn*64 + gq)*AST + tg;
            #pragma unroll
            for (int ks = 0; ks < 4; ks++) {
                int k0 = ks*8;
                uint32_t af[2][4];
                #pragma unroll
                for (int mf = 0; mf < 2; mf++) {
                    const float* ap = Aw + mf*16*AST + k0;
                    af[mf][0] = __float_as_uint(ap[0]);
                    af[mf][1] = __float_as_uint(ap[8*AST]);
                    af[mf][2] = __float_as_uint(ap[4]);
                    af[mf][3] = __float_as_uint(ap[8*AST + 4]);
                }
                uint32_t bf[8][2];
                #pragma unroll
                for (int nf = 0; nf < 8; nf++) {
                    const float* bp = Bw + nf*8*AST + k0;
                    bf[nf][0] = __float_as_uint(bp[0]);
                    bf[nf][1] = __float_as_uint(bp[4]);
                }
                #pragma unroll
                for (int mf = 0; mf < 2; mf++)
                    #pragma unroll
                    for (int nf = 0; nf < 8; nf++)
                        mma_tf32(acc[mf][nf], af[mf], bf[nf]);
            }
        }
    }

    // finalize in fragment space: BN2 + residual + ReLU, then transpose via Ds
    __syncthreads();
    float* Ds = dsm;   // [128 p][DST]
    const float* rT = g_resT + ((size_t)n*P + pbase)*COUT;
    #pragma unroll
    for (int mf = 0; mf < 2; mf++) {
        int r0 = wm*32 + mf*16 + gq;
        #pragma unroll
        for (int nf = 0; nf < 8; nf++) {
            int c0 = wn*64 + nf*8 + tg*2;
            float2 ra = *reinterpret_cast<const float2*>(rT + (size_t)r0*COUT + c0);
            float2 rb = *reinterpret_cast<const float2*>(rT + (size_t)(r0+8)*COUT + c0);
            float s2a = s_s2[c0], s2b = s_s2[c0+1];
            float o2a = s_o2[c0], o2b = s_o2[c0+1];
            float w00 = fmaf(s2a, acc[mf][nf][0], o2a) + ra.x;
            float w01 = fmaf(s2b, acc[mf][nf][1], o2b) + ra.y;
            float w10 = fmaf(s2a, acc[mf][nf][2], o2a) + rb.x;
            float w11 = fmaf(s2b, acc[mf][nf][3], o2b) + rb.y;
            Ds[r0*DST + c0]       = w00 > 0.f ? w00 : 0.f;
            Ds[r0*DST + c0 + 1]   = w01 > 0.f ? w01 : 0.f;
            Ds[(r0+8)*DST + c0]   = w10 > 0.f ? w10 : 0.f;
            Ds[(r0+8)*DST + c0+1] = w11 > 0.f ? w11 : 0.f;
        }
    }
    __syncthreads();

    {
        int o = tid >> 1, half = tid & 1;
        size_t gbase = ((size_t)n*COUT + o)*P + pbase + half*64;
        float4* op = reinterpret_cast<float4*>(out + gbase);
        #pragma unroll 4
        for (int j4 = 0; j4 < 16; j4++) {
            int pl = half*64 + j4*4;
            float4 w;
            w.x = Ds[(pl+0)*DST + o];
            w.y = Ds[(pl+1)*DST + o];
            w.z = Ds[(pl+2)*DST + o];
            w.w = Ds[(pl+3)*DST + o];
            op[j4] = w;
        }
    }
}

// ---------------------------------------------------------------------------
extern "C" void kernel_launch(void* const* d_in, const int* in_sizes, int n_in,
                              void* d_out, int out_size) {
    const float* x    = (const float*)d_in[0];
    const float* A    = (const float*)d_in[1];
    // d_in[2], d_in[3] = w1, b1 -- cancel in softmax
    const float* w2   = (const float*)d_in[4];
    const float* b2   = (const float*)d_in[5];
    const float* w3   = (const float*)d_in[6];
    const float* b3   = (const float*)d_in[7];
    const float* w4   = (const float*)d_in[8];
    const float* b4   = (const float*)d_in[9];
    const float* bn1g = (const float*)d_in[10];
    const float* bn1b = (const float*)d_in[11];
    const float* bn1m = (const float*)d_in[12];
    const float* bn1v = (const float*)d_in[13];
    const float* wt   = (const float*)d_in[14];
    const float* bt   = (const float*)d_in[15];
    const float* bn2g = (const float*)d_in[16];
    const float* bn2b = (const float*)d_in[17];
    const float* bn2m = (const float*)d_in[18];
    const float* bn2v = (const float*)d_in[19];
    const float* wr   = (const float*)d_in[20];
    const float* br   = (const float*)d_in[21];
    const float* bnrg = (const float*)d_in[22];
    const float* bnrb = (const float*)d_in[23];
    const float* bnrm = (const float*)d_in[24];
    const float* bnrv = (const float*)d_in[25];
    float* out = (float*)d_out;

    static const int AS_F  = 64*KST;       // 8960 floats
    static const int YT_F  = 384*YTS;      // 20352 floats
    static const int FRONT_SMEM = (AS_F > YT_F ? AS_F : YT_F) * 4;     // 81408 B
    static const int TCN_SMEM   = (128*DST > AROWS*AST + 128*AST ?
                                   128*DST : AROWS*AST + 128*AST) * 4; // 68096 B
    cudaFuncSetAttribute(k_front,   cudaFuncAttributeMaxDynamicSharedMemorySize, FRONT_SMEM);
    cudaFuncSetAttribute(k_tcn_mma, cudaFuncAttributeMaxDynamicSharedMemorySize, TCN_SMEM);

    k_mean<<<NB*CIN, 256>>>(x);
    k_soft<<<NB*ICH, 32>>>(w2, b2);
    k_wprep<<<(9*COUT*COUT + 255)/256, 256>>>(wt);
    k_bprep<<<(2*8*8*6*64 + 255)/256, 256>>>(w3, w4, wr);
    k_front<<<dim3(128, NB), 256, FRONT_SMEM>>>(
        x, A, b3, b4, br,
        bn1g, bn1b, bn1m, bn1v, bnrg, bnrb, bnrm, bnrv);
    k_tcn_mma<<<dim3(50, NB), 256, TCN_SMEM>>>(
        bt, bn2g, bn2b, bn2m, bn2v, out);
}

// round 12
// speedup vs baseline: 1.5216x; 1.4682x over previous
#include <cuda_runtime.h>
#include <math.h>
#include <stdint.h>

#define NB   32
#define CIN  64
#define COUT 128
#define TT   256
#define V    25
#define ICH  32
#define P    6400          // TT*V flat positions per (n, channel)
#define EPSF 1e-5f

// ---------------------------------------------------------------------------
// Scratch (device globals: allocation-free rule)
// ---------------------------------------------------------------------------
__device__ __align__(16) float g_resT[(size_t)NB*P*COUT];  // residual fp32 [n][p][o]
__device__ __align__(16) float g_hT [(size_t)NB*P*COUT];   // h (tf32-rounded) [n][p][c]
__device__ __align__(16) float g_wtT[9*COUT*COUT];         // wt (tf32-rounded) [dt][o][c]
__device__ float g_xm[NB*CIN*V];
__device__ float g_s[NB*ICH*V];

__device__ __forceinline__ float tf32r(float x) {
    uint32_t r;
    asm("cvt.rna.tf32.f32 %0, %1;" : "=r"(r) : "f"(x));
    return __uint_as_float(r);
}

__device__ __forceinline__ void mma_tf32(float* c, const uint32_t* a, const uint32_t* b) {
    asm volatile(
        "mma.sync.aligned.m16n8k8.row.col.f32.tf32.tf32.f32 "
        "{%0,%1,%2,%3}, {%4,%5,%6,%7}, {%8,%9}, {%0,%1,%2,%3};"
        : "+f"(c[0]), "+f"(c[1]), "+f"(c[2]), "+f"(c[3])
        : "r"(a[0]), "r"(a[1]), "r"(a[2]), "r"(a[3]), "r"(b[0]), "r"(b[1]));
}

__device__ __forceinline__ void cp_async16(uint32_t saddr, const void* g, uint32_t nbytes) {
    asm volatile("cp.async.cg.shared.global [%0], [%1], 16, %2;"
                 :: "r"(saddr), "l"(g), "r"(nbytes));
}
#define CP_COMMIT() asm volatile("cp.async.commit_group;" ::: "memory")
#define CP_WAIT0()  asm volatile("cp.async.wait_group 0;" ::: "memory")

__device__ __forceinline__ uint32_t s2u(const void* p) {
    return (uint32_t)__cvta_generic_to_shared(p);
}

// ---------------------------------------------------------------------------
// Kernel 1: xm[n,c,v] = mean_t x[n,c,t,v]
// ---------------------------------------------------------------------------
__global__ void k_mean(const float* __restrict__ x) {
    int b = blockIdx.x;
    const float* xp = x + (size_t)b * TT * V;
    int v = threadIdx.x & 31, tg = threadIdx.x >> 5;
    float s = 0.f;
    if (v < V) for (int t = tg; t < TT; t += 8) s += xp[t*V + v];
    __shared__ float sm[8][32];
    sm[tg][v] = s;
    __syncthreads();
    if (tg == 0 && v < V) {
        float tot = 0.f;
        #pragma unroll
        for (int g = 0; g < 8; g++) tot += sm[g][v];
        g_xm[b*V + v] = tot * (1.f / TT);
    }
}

// ---------------------------------------------------------------------------
// Kernel 2: s[n,i,v] = softmax_v( -(w2@xm + b2) )   (x1 cancels in softmax)
// ---------------------------------------------------------------------------
__global__ void k_soft(const float* __restrict__ w2, const float* __restrict__ b2) {
    int n = blockIdx.x >> 5, i = blockIdx.x & 31;
    int v = threadIdx.x;
    float z = -1e30f;
    if (v < V) {
        float acc = b2[i];
        const float* w  = w2 + i*CIN;
        const float* xm = g_xm + n*CIN*V;
        #pragma unroll 8
        for (int c = 0; c < CIN; c++) acc = fmaf(w[c], xm[c*V + v], acc);
        z = -acc;
    }
    float m = z;
    #pragma unroll
    for (int off = 16; off; off >>= 1) m = fmaxf(m, __shfl_xor_sync(~0u, m, off));
    float e = (v < V) ? expf(z - m) : 0.f;
    float ssum = e;
    #pragma unroll
    for (int off = 16; off; off >>= 1) ssum += __shfl_xor_sync(~0u, ssum, off);
    if (v < V) g_s[(n*ICH + i)*V + v] = e / ssum;
}

// ---------------------------------------------------------------------------
// Kernel 2b: wt -> [dt][o][c] fp32, tf32-rounded
// ---------------------------------------------------------------------------
__global__ void k_wprep(const float* __restrict__ wt) {
    int idx = blockIdx.x * 256 + threadIdx.x;
    if (idx >= 9*COUT*COUT) return;
    int dt = idx / (COUT*COUT), r = idx % (COUT*COUT);
    int o = r / COUT, c = r % COUT;
    g_wtT[idx] = tf32r(wt[((size_t)o*COUT + c)*9 + dt]);
}

// ---------------------------------------------------------------------------
// Kernel 3: front end. Per block (n, ptile of 100):
//   Y[100(pad128),384] = X^T x [w3;w4;wr]^T (tf32 single-pass);
//   epilogue via transposed Yt[384][101]: softmax-y1, A-mix,
//   BN1+ReLU -> g_hT (direct coalesced), BNr -> g_resT.
// 512 threads = 16 warps (2M x 8N), warp tile 64x48.
// ---------------------------------------------------------------------------
#define KST 68     // A/B smem stride
#define YTS 101    // Yt stride (>=100 rows, odd -> conflict-free epilogue reads)

__global__ void __launch_bounds__(512, 1) k_front(
    const float* __restrict__ x,  const float* __restrict__ A,
    const float* __restrict__ w3, const float* __restrict__ b3,
    const float* __restrict__ w4, const float* __restrict__ b4,
    const float* __restrict__ wr, const float* __restrict__ br,
    const float* __restrict__ bn1g, const float* __restrict__ bn1b,
    const float* __restrict__ bn1m, const float* __restrict__ bn1v,
    const float* __restrict__ bnrg, const float* __restrict__ bnrb,
    const float* __restrict__ bnrm, const float* __restrict__ bnrv)
{
    extern __shared__ __align__(16) float dsm[];
    __shared__ float sA[625], ss[800];
    __shared__ float sb3[128], sb4[128], sc1[128], so1[128], scr[128], sofr[128];

    const int tid = threadIdx.x;
    const int n = blockIdx.y;
    const int pbase = blockIdx.x * 100;

    for (int idx = tid; idx < 625; idx += 512) sA[idx] = A[idx];
    for (int idx = tid; idx < 800; idx += 512) ss[idx] = g_s[n*800 + idx];
    if (tid < 128) {
        float s1 = bn1g[tid] / sqrtf(bn1v[tid] + EPSF);
        sc1[tid] = s1;
        so1[tid] = bn1b[tid] - bn1m[tid]*s1;
        float sr = bnrg[tid] / sqrtf(bnrv[tid] + EPSF);
        scr[tid] = sr;
        sofr[tid] = sr*br[tid] + (bnrb[tid] - bnrm[tid]*sr);
        sb3[tid] = b3[tid];
        sb4[tid] = b4[tid];
    }

    float* As = dsm;               // [128][KST]
    float* Bs = dsm + 128*KST;     // [384][KST]

    // stage A = X^T (transpose during store, tf32-rounded); rows 100..127 zero
    const float* xn = x + (size_t)n*CIN*P + pbase;
    for (int idx = tid; idx < 1600; idx += 512) {
        int c = idx / 25, q = idx % 25;
        float4 v = *reinterpret_cast<const float4*>(xn + (size_t)c*P + q*4);
        int r = q*4;
        As[(r+0)*KST + c] = tf32r(v.x);
        As[(r+1)*KST + c] = tf32r(v.y);
        As[(r+2)*KST + c] = tf32r(v.z);
        As[(r+3)*KST + c] = tf32r(v.w);
    }
    for (int idx = tid; idx < 28*64; idx += 512)
        As[(100 + idx/64)*KST + (idx & 63)] = 0.f;

    // stage B = [w3; w4; wr], tf32-rounded, [384][64] row-major
    for (int idx = tid; idx < 6144; idx += 512) {
        int r = idx >> 4, q = idx & 15;
        const float* src = (r < 128) ? (w3 + r*64) :
                           (r < 256) ? (w4 + (r-128)*64) : (wr + (r-256)*64);
        float4 v = *reinterpret_cast<const float4*>(src + q*4);
        float* d = &Bs[r*KST + q*4];
        d[0] = tf32r(v.x); d[1] = tf32r(v.y); d[2] = tf32r(v.z); d[3] = tf32r(v.w);
    }
    __syncthreads();

    // MMA: 16 warps 2M x 8N, warp tile 64 x 48
    const int wid = tid >> 5, lid = tid & 31;
    const int gq = lid >> 2, tg = lid & 3;
    const int wm = wid >> 3, wn = wid & 7;

    float acc[4][6][4];
    #pragma unroll
    for (int mf = 0; mf < 4; mf++)
        #pragma unroll
        for (int nf = 0; nf < 6; nf++)
            #pragma unroll
            for (int q = 0; q < 4; q++) acc[mf][nf][q] = 0.f;

    const float* Ab = As + (wm*64 + gq)*KST + tg;
    const float* Bb = Bs + (wn*48 + gq)*KST + tg;
    #pragma unroll
    for (int ks = 0; ks < 8; ks++) {
        int k0 = ks*8;
        uint32_t af[4][4];
        #pragma unroll
        for (int mf = 0; mf < 4; mf++) {
            const float* ap = Ab + mf*16*KST + k0;
            af[mf][0] = __float_as_uint(ap[0]);
            af[mf][1] = __float_as_uint(ap[8*KST]);
            af[mf][2] = __float_as_uint(ap[4]);
            af[mf][3] = __float_as_uint(ap[8*KST + 4]);
        }
        #pragma unroll
        for (int nf = 0; nf < 6; nf++) {
            const float* bp = Bb + nf*8*KST + k0;
            uint32_t bf[2];
            bf[0] = __float_as_uint(bp[0]);
            bf[1] = __float_as_uint(bp[4]);
            #pragma unroll
            for (int mf = 0; mf < 4; mf++) mma_tf32(acc[mf][nf], af[mf], bf);
        }
    }
    __syncthreads();   // staging consumed

    // frags -> Yt[384][YTS] (transposed; r0 in 0..99 < YTS)
    float* Yt = dsm;
    #pragma unroll
    for (int mf = 0; mf < 4; mf++) {
        int r0 = wm*64 + mf*16 + gq;
        #pragma unroll
        for (int nf = 0; nf < 6; nf++) {
            int c0 = wn*48 + nf*8 + tg*2;
            if (r0 < 100) {
                Yt[c0*YTS + r0]     = acc[mf][nf][0];
                Yt[(c0+1)*YTS + r0] = acc[mf][nf][1];
            }
            if (r0 + 8 < 100) {
                Yt[c0*YTS + r0 + 8]     = acc[mf][nf][2];
                Yt[(c0+1)*YTS + r0 + 8] = acc[mf][nf][3];
            }
        }
    }
    __syncthreads();

    // epilogue: thread = (o, t), t in 0..3; direct coalesced drains
    {
        const int o = tid & 127, t = tid >> 7;
        float p3[V], p4[V], pr[V];
        const float* y3 = Yt + o*YTS + t*25;
        const float* y4 = Yt + (128 + o)*YTS + t*25;
        const float* yr = Yt + (256 + o)*YTS + t*25;
        float b4v = sb4[o];
        #pragma unroll
        for (int v = 0; v < V; v++) {
            p3[v] = y3[v];
            p4[v] = y4[v] + b4v;
            pr[v] = yr[v];
        }
        float y1 = sb3[o];
        const float* sv = ss + (o & 31)*V;
        #pragma unroll
        for (int v = 0; v < V; v++) y1 = fmaf(sv[v], p3[v], y1);

        float s1 = sc1[o], o1 = so1[o];
        float* hdst = g_hT + ((size_t)n*P + pbase)*COUT;
        #pragma unroll 5
        for (int u = 0; u < V; u++) {
            float a = y1;
            const float* Ar = sA + u*V;
            #pragma unroll
            for (int v = 0; v < V; v++) a = fmaf(Ar[v], p4[v], a);
            float h = fmaf(s1, a, o1);
            hdst[(size_t)(t*25 + u)*COUT + o] = tf32r(h > 0.f ? h : 0.f);
        }
        float sr = scr[o], ofr = sofr[o];
        float* rdst = g_resT + ((size_t)n*P + pbase)*COUT;
        #pragma unroll
        for (int v = 0; v < V; v++)
            rdst[(size_t)(t*25 + v)*COUT + o] = fmaf(sr, pr[v], ofr);
    }
}

// ---------------------------------------------------------------------------
// Kernel 4: temporal conv, 9 shifted GEMMs via mma.sync tf32.
// cp.async double-buffered B (overlaps next-B load with current mma);
// epilogue: BN2 + residual (fragment space) + ReLU, Ds transpose, out.
// ---------------------------------------------------------------------------
#define AST 36
#define DST 133
#define AROWS 328

__global__ void __launch_bounds__(256, 2) k_tcn_mma(
    const float* __restrict__ bt,
    const float* __restrict__ bn2g, const float* __restrict__ bn2b,
    const float* __restrict__ bn2m, const float* __restrict__ bn2v,
    float* __restrict__ out)
{
    extern __shared__ __align__(16) float dsm[];
    float* As  = dsm;                        // [AROWS][AST]
    float* Bs0 = dsm + AROWS*AST;            // [128][AST]
    float* Bs1 = Bs0 + 128*AST;              // [128][AST]
    __shared__ float s_s2[COUT], s_o2[COUT];

    const int tid = threadIdx.x, wid = tid >> 5, lid = tid & 31;
    const int gq = lid >> 2, tg = lid & 3;
    const int wm = wid >> 1, wn = wid & 1;
    const int n = blockIdx.y;
    const int pbase = blockIdx.x * 128;

    if (tid < COUT) {
        float s2 = bn2g[tid] / sqrtf(bn2v[tid] + EPSF);
        s_s2[tid] = s2;
        s_o2[tid] = bn2b[tid] - bn2m[tid]*s2 + s2*bt[tid];
    }

    float acc[2][8][4];
    #pragma unroll
    for (int mf = 0; mf < 2; mf++)
        #pragma unroll
        for (int nf = 0; nf < 8; nf++)
            #pragma unroll
            for (int q = 0; q < 4; q++) acc[mf][nf][q] = 0.f;

    const float* hbase = g_hT + (size_t)n * P * COUT;
    float* bufs[2] = { Bs0, Bs1 };
    int buf = 0;

    // prefetch B(it=0): ck=0, dt=0
    {
        #pragma unroll
        for (int i = 0; i < 4; i++) {
            int idx = tid + i*256;
            int r = idx >> 3, q = idx & 7;
            cp_async16(s2u(Bs0 + r*AST + q*4),
                       g_wtT + (size_t)r*COUT + q*4, 16);
        }
        CP_COMMIT();
    }

    #pragma unroll 1
    for (int it = 0; it < 36; it++) {
        int ck = it / 9, dt = it % 9;

        CP_WAIT0();          // B(it) landed
        __syncthreads();     // all see B(it); prior mma done (A/B overwrite safe)

        if (dt == 0) {
            // stage A(ck): extended tile via cp.async (zfill OOB)
            #pragma unroll 1
            for (int idx = tid; idx < AROWS*8; idx += 256) {
                int r = idx >> 3, q = idx & 7;
                int gp = pbase - 100 + r;
                uint32_t ok = ((unsigned)gp < (unsigned)P) ? 16u : 0u;
                int gpc = ok ? gp : 0;
                cp_async16(s2u(As + r*AST + q*4),
                           hbase + (size_t)gpc*COUT + ck*32 + q*4, ok);
            }
            CP_COMMIT();
            CP_WAIT0();
            __syncthreads();
        }

        // prefetch B(it+1) into alternate buffer (overlaps mma below)
        if (it + 1 < 36) {
            int ck2 = (it + 1) / 9, dt2 = (it + 1) % 9;
            float* bd = bufs[buf ^ 1];
            #pragma unroll
            for (int i = 0; i < 4; i++) {
                int idx = tid + i*256;
                int r = idx >> 3, q = idx & 7;
                cp_async16(s2u(bd + r*AST + q*4),
                           g_wtT + ((size_t)dt2*COUT + r)*COUT + ck2*32 + q*4, 16);
            }
            CP_COMMIT();
        }

        const float* Aw = As + (dt*25 + wm*32 + gq)*AST + tg;
        const float* Bw = bufs[buf] + (wn*64 + gq)*AST + tg;
        #pragma unroll
        for (int ks = 0; ks < 4; ks++) {
            int k0 = ks*8;
            uint32_t af[2][4];
            #pragma unroll
            for (int mf = 0; mf < 2; mf++) {
                const float* ap = Aw + mf*16*AST + k0;
                af[mf][0] = __float_as_uint(ap[0]);
                af[mf][1] = __float_as_uint(ap[8*AST]);
                af[mf][2] = __float_as_uint(ap[4]);
                af[mf][3] = __float_as_uint(ap[8*AST + 4]);
            }
            uint32_t bf[8][2];
            #pragma unroll
            for (int nf = 0; nf < 8; nf++) {
                const float* bp = Bw + nf*8*AST + k0;
                bf[nf][0] = __float_as_uint(bp[0]);
                bf[nf][1] = __float_as_uint(bp[4]);
            }
            #pragma unroll
            for (int mf = 0; mf < 2; mf++)
                #pragma unroll
                for (int nf = 0; nf < 8; nf++)
                    mma_tf32(acc[mf][nf], af[mf], bf[nf]);
        }
        buf ^= 1;
    }

    // finalize in fragment space: BN2 + residual + ReLU, transpose via Ds
    __syncthreads();
    float* Ds = dsm;   // [128 p][DST]
    const float* rT = g_resT + ((size_t)n*P + pbase)*COUT;
    #pragma unroll
    for (int mf = 0; mf < 2; mf++) {
        int r0 = wm*32 + mf*16 + gq;
        #pragma unroll
        for (int nf = 0; nf < 8; nf++) {
            int c0 = wn*64 + nf*8 + tg*2;
            float2 ra = *reinterpret_cast<const float2*>(rT + (size_t)r0*COUT + c0);
            float2 rb = *reinterpret_cast<const float2*>(rT + (size_t)(r0+8)*COUT + c0);
            float s2a = s_s2[c0], s2b = s_s2[c0+1];
            float o2a = s_o2[c0], o2b = s_o2[c0+1];
            float w00 = fmaf(s2a, acc[mf][nf][0], o2a) + ra.x;
            float w01 = fmaf(s2b, acc[mf][nf][1], o2b) + ra.y;
            float w10 = fmaf(s2a, acc[mf][nf][2], o2a) + rb.x;
            float w11 = fmaf(s2b, acc[mf][nf][3], o2b) + rb.y;
            Ds[r0*DST + c0]       = w00 > 0.f ? w00 : 0.f;
            Ds[r0*DST + c0 + 1]   = w01 > 0.f ? w01 : 0.f;
            Ds[(r0+8)*DST + c0]   = w10 > 0.f ? w10 : 0.f;
            Ds[(r0+8)*DST + c0+1] = w11 > 0.f ? w11 : 0.f;
        }
    }
    __syncthreads();

    {
        int o = tid >> 1, half = tid & 1;
        size_t gbase = ((size_t)n*COUT + o)*P + pbase + half*64;
        float4* op = reinterpret_cast<float4*>(out + gbase);
        #pragma unroll 4
        for (int j4 = 0; j4 < 16; j4++) {
            int pl = half*64 + j4*4;
            float4 w;
            w.x = Ds[(pl+0)*DST + o];
            w.y = Ds[(pl+1)*DST + o];
            w.z = Ds[(pl+2)*DST + o];
            w.w = Ds[(pl+3)*DST + o];
            op[j4] = w;
        }
    }
}

// ---------------------------------------------------------------------------
extern "C" void kernel_launch(void* const* d_in, const int* in_sizes, int n_in,
                              void* d_out, int out_size) {
    const float* x    = (const float*)d_in[0];
    const float* A    = (const float*)d_in[1];
    // d_in[2], d_in[3] = w1, b1 -- cancel in softmax
    const float* w2   = (const float*)d_in[4];
    const float* b2   = (const float*)d_in[5];
    const float* w3   = (const float*)d_in[6];
    const float* b3   = (const float*)d_in[7];
    const float* w4   = (const float*)d_in[8];
    const float* b4   = (const float*)d_in[9];
    const float* bn1g = (const float*)d_in[10];
    const float* bn1b = (const float*)d_in[11];
    const float* bn1m = (const float*)d_in[12];
    const float* bn1v = (const float*)d_in[13];
    const float* wt   = (const float*)d_in[14];
    const float* bt   = (const float*)d_in[15];
    const float* bn2g = (const float*)d_in[16];
    const float* bn2b = (const float*)d_in[17];
    const float* bn2m = (const float*)d_in[18];
    const float* bn2v = (const float*)d_in[19];
    const float* wr   = (const float*)d_in[20];
    const float* br   = (const float*)d_in[21];
    const float* bnrg = (const float*)d_in[22];
    const float* bnrb = (const float*)d_in[23];
    const float* bnrm = (const float*)d_in[24];
    const float* bnrv = (const float*)d_in[25];
    float* out = (float*)d_out;

    static const int STAGE_F = 128*KST + 384*KST;    // 34816 floats
    static const int YT_F    = 384*YTS;              // 38784 floats
    static const int FRONT_SMEM = (STAGE_F > YT_F ? STAGE_F : YT_F) * 4;  // 155136 B
    static const int TCN_F  = AROWS*AST + 2*128*AST; // 21024 floats
    static const int TCN_SMEM = (128*DST > TCN_F ? 128*DST : TCN_F) * 4;  // 84096 B
    cudaFuncSetAttribute(k_front,   cudaFuncAttributeMaxDynamicSharedMemorySize, FRONT_SMEM);
    cudaFuncSetAttribute(k_tcn_mma, cudaFuncAttributeMaxDynamicSharedMemorySize, TCN_SMEM);

    k_mean<<<NB*CIN, 256>>>(x);
    k_soft<<<NB*ICH, 32>>>(w2, b2);
    k_wprep<<<(9*COUT*COUT + 255)/256, 256>>>(wt);
    k_front<<<dim3(64, NB), 512, FRONT_SMEM>>>(
        x, A, w3, b3, w4, b4, wr, br,
        bn1g, bn1b, bn1m, bn1v, bnrg, bnrb, bnrm, bnrv);
    k_tcn_mma<<<dim3(50, NB), 256, TCN_SMEM>>>(
        bt, bn2g, bn2b, bn2m, bn2v, out);
}